// round 12
// baseline (speedup 1.0000x reference)
#include <cuda_runtime.h>
#include <cuda_fp16.h>
#include <cstdint>

#define N_NODES 40000
#define N_EDGES 640000
#define F 128
#define SCALE_INV 0.08838834764831845f   // 1/sqrt(128)

#define NBLK 157            // ceil(40000/256) scan blocks

#define LDA 132
#define LDB 136
#define SMEM_BYTES ((128 * LDA + 128 * LDB) * 4)   // 137216 B

// ---- static scratch ----
// Interleaved K/H (fp16): per node, 32 groups of 8 halves (512 B per node):
//   [g*8+0..3] = K cols 4g..4g+3,  [g*8+4..7] = H cols 4g..4g+3
__device__ __half g_KH[N_NODES * 2 * F];
__device__ float  g_Q [N_NODES * F];     // (feat @ Wq) * (1/sqrt(F))  fp32
__device__ int    g_deg[N_NODES];        // stays zero between invocations
__device__ int    g_rowStart[N_NODES + 1];
__device__ int    g_rank[N_EDGES];       // edge's rank within its dst node
__device__ int    g_srcOff[N_EDGES];     // src node id << 9 (BYTE offset in g_KH)
__device__ int    g_bsum[NBLK];

// ---------------------------------------------------------------------------
// hist: count degrees AND record each edge's arrival rank (atomicAdd return).
__global__ void hist_kernel(const int* __restrict__ dst) {
    int base = (blockIdx.x * blockDim.x + threadIdx.x) << 2;   // 4 edges/thread
    if (base + 3 < N_EDGES) {
        int4 d = *(const int4*)(dst + base);
        int4 r;
        r.x = atomicAdd(&g_deg[d.x], 1);
        r.y = atomicAdd(&g_deg[d.y], 1);
        r.z = atomicAdd(&g_deg[d.z], 1);
        r.w = atomicAdd(&g_deg[d.w], 1);
        *(int4*)(g_rank + base) = r;
    } else {
        for (int e = base; e < N_EDGES; e++)
            g_rank[e] = atomicAdd(&g_deg[__ldg(&dst[e])], 1);
    }
}

// block-local exclusive scan of deg -> rowStart(local), block totals -> bsum.
// Zeroes g_deg after reading (invariant for next invocation).
__global__ __launch_bounds__(256) void scan1_kernel() {
    __shared__ int s[256];
    int tid = threadIdx.x;
    int i = blockIdx.x * 256 + tid;
    int v = 0;
    if (i < N_NODES) { v = g_deg[i]; g_deg[i] = 0; }
    s[tid] = v;
    __syncthreads();
#pragma unroll
    for (int off = 1; off < 256; off <<= 1) {
        int t = (tid >= off) ? s[tid - off] : 0;
        __syncthreads();
        s[tid] += t;
        __syncthreads();
    }
    if (i < N_NODES) g_rowStart[i] = s[tid] - v;
    if (tid == 255) g_bsum[blockIdx.x] = s[255];
}

// add block offsets (each block reduces bsum[t < blockIdx] itself); sentinel.
__global__ __launch_bounds__(256) void scan23_kernel() {
    __shared__ int red[256];
    int tid = threadIdx.x;
    int v = (tid < NBLK && tid < blockIdx.x) ? g_bsum[tid] : 0;
    red[tid] = v;
    __syncthreads();
#pragma unroll
    for (int off = 128; off > 0; off >>= 1) {
        if (tid < off) red[tid] += red[tid + off];
        __syncthreads();
    }
    int offset = red[0];

    int i = blockIdx.x * 256 + tid;
    if (i < N_NODES) g_rowStart[i] += offset;
    if (i == 0) g_rowStart[N_NODES] = N_EDGES;
}

// atomic-free scatter: slot = rowStart[dst] + rank[edge]
__global__ void scatter_kernel(const int* __restrict__ src,
                               const int* __restrict__ dst) {
    int base = (blockIdx.x * blockDim.x + threadIdx.x) << 2;   // 4 edges/thread
    if (base + 3 < N_EDGES) {
        int4 d = *(const int4*)(dst + base);
        int4 s = *(const int4*)(src + base);
        int4 r = *(const int4*)(g_rank + base);
        g_srcOff[g_rowStart[d.x] + r.x] = s.x << 9;
        g_srcOff[g_rowStart[d.y] + r.y] = s.y << 9;
        g_srcOff[g_rowStart[d.z] + r.z] = s.z << 9;
        g_srcOff[g_rowStart[d.w] + r.w] = s.w << 9;
    } else {
        for (int e = base; e < N_EDGES; e++) {
            int d = __ldg(&dst[e]);
            g_srcOff[g_rowStart[d] + g_rank[e]] = __ldg(&src[e]) << 9;
        }
    }
}

// ---------------------------------------------------------------------------
__device__ __forceinline__ uint32_t f2tf32(float x) {
    uint32_t r;
    asm("cvt.rna.tf32.f32 %0, %1;" : "=r"(r) : "f"(x));
    return r;
}

// Fused 3-way GEMM (tf32 tensor cores): one 128x128 row tile per CTA;
// A staged ONCE, the three weights staged sequentially into Bs.
// H (j=0) and K (j=2) write fp16 into the interleaved g_KH; Q (j=1) fp32,
// pre-scaled by 1/sqrt(F).
__global__ __launch_bounds__(256) void gemm3_tf32_kernel(
    const float* __restrict__ feat,
    const float* __restrict__ Wfc,
    const float* __restrict__ Wq,
    const float* __restrict__ Wk)
{
    extern __shared__ float sm[];
    float* As = sm;                 // [128][LDA]
    float* Bs = sm + 128 * LDA;     // [128][LDB]

    const int tid  = threadIdx.x;
    const int row0 = blockIdx.x * 128;

    for (int i = tid; i < 4096; i += 256) {
        int r = i >> 5, c4 = (i & 31) << 2;
        float4 v = make_float4(0.f, 0.f, 0.f, 0.f);
        if (row0 + r < N_NODES)
            v = *(const float4*)(feat + (size_t)(row0 + r) * F + c4);
        *(float4*)(As + r * LDA + c4) = v;
    }

    const int wid  = tid >> 5;
    const int lane = tid & 31;
    const int wm   = (wid & 3) << 5;
    const int wn   = (wid >> 2) << 6;
    const int grp  = lane >> 2;
    const int qid  = lane & 3;

    const float* Ws[3] = { Wfc, Wq, Wk };

#pragma unroll
    for (int j = 0; j < 3; j++) {
        __syncthreads();
        const float* W = Ws[j];
        for (int i = tid; i < 4096; i += 256) {
            int r = i >> 5, c4 = (i & 31) << 2;
            *(float4*)(Bs + r * LDB + c4) = *(const float4*)(W + r * F + c4);
        }
        __syncthreads();

        float acc[2][8][4];
#pragma unroll
        for (int mi = 0; mi < 2; mi++)
#pragma unroll
            for (int nt = 0; nt < 8; nt++)
#pragma unroll
                for (int c = 0; c < 4; c++) acc[mi][nt][c] = 0.0f;

#pragma unroll
        for (int ks = 0; ks < 16; ks++) {
            const int k0 = ks << 3;
            uint32_t a[2][4];
#pragma unroll
            for (int mi = 0; mi < 2; mi++) {
                const int rb = wm + (mi << 4);
                a[mi][0] = f2tf32(As[(rb + grp)     * LDA + k0 + qid]);
                a[mi][1] = f2tf32(As[(rb + grp + 8) * LDA + k0 + qid]);
                a[mi][2] = f2tf32(As[(rb + grp)     * LDA + k0 + qid + 4]);
                a[mi][3] = f2tf32(As[(rb + grp + 8) * LDA + k0 + qid + 4]);
            }
#pragma unroll
            for (int nt = 0; nt < 8; nt++) {
                const int n0 = wn + (nt << 3);
                uint32_t b0 = f2tf32(Bs[(k0 + qid)     * LDB + n0 + grp]);
                uint32_t b1 = f2tf32(Bs[(k0 + qid + 4) * LDB + n0 + grp]);
#pragma unroll
                for (int mi = 0; mi < 2; mi++) {
                    asm volatile(
                        "mma.sync.aligned.m16n8k8.row.col.f32.tf32.tf32.f32 "
                        "{%0,%1,%2,%3}, {%4,%5,%6,%7}, {%8,%9}, {%0,%1,%2,%3};"
                        : "+f"(acc[mi][nt][0]), "+f"(acc[mi][nt][1]),
                          "+f"(acc[mi][nt][2]), "+f"(acc[mi][nt][3])
                        : "r"(a[mi][0]), "r"(a[mi][1]), "r"(a[mi][2]),
                          "r"(a[mi][3]), "r"(b0), "r"(b1));
                }
            }
        }

        const int khOff = (j == 0) ? 4 : 0;   // H -> slot+4, K -> slot+0
#pragma unroll
        for (int mi = 0; mi < 2; mi++) {
            const int r = row0 + wm + (mi << 4) + grp;
#pragma unroll
            for (int nt = 0; nt < 8; nt++) {
                const int col = wn + (nt << 3) + (qid << 1);   // col even
                if (j == 1) {          // Q fp32, pre-scaled
                    if (r < N_NODES)
                        *(float2*)(g_Q + (size_t)r * F + col) =
                            make_float2(acc[mi][nt][0] * SCALE_INV,
                                        acc[mi][nt][1] * SCALE_INV);
                    if (r + 8 < N_NODES)
                        *(float2*)(g_Q + (size_t)(r + 8) * F + col) =
                            make_float2(acc[mi][nt][2] * SCALE_INV,
                                        acc[mi][nt][3] * SCALE_INV);
                } else {               // H/K fp16 interleaved
                    const int slot = ((col >> 2) << 3) + khOff + (col & 3);
                    if (r < N_NODES)
                        *(__half2*)(g_KH + (size_t)r * 256 + slot) =
                            __floats2half2_rn(acc[mi][nt][0], acc[mi][nt][1]);
                    if (r + 8 < N_NODES)
                        *(__half2*)(g_KH + (size_t)(r + 8) * 256 + slot) =
                            __floats2half2_rn(acc[mi][nt][2], acc[mi][nt][3]);
                }
            }
        }
    }
}

// ---------------------------------------------------------------------------
// Fused attention: one warp per dst node; 8 LANES PER EDGE, 4 edges
// concurrently. Lane (t = lane&7) owns dims [16t..16t+15] of its group's
// edge (4 x LDG.128 = 64 B of interleaved K/H quads). In-group dot reduce =
// 3 shfls; exp computed locally (no broadcast). Cross-group combine once
// per node.
// ---------------------------------------------------------------------------
__device__ __forceinline__ void unp(uint4 r, float* kf, float* hf) {
    float2 a = __half22float2(*(__half2*)&r.x);
    float2 b = __half22float2(*(__half2*)&r.y);
    float2 c = __half22float2(*(__half2*)&r.z);
    float2 d = __half22float2(*(__half2*)&r.w);
    kf[0] = a.x; kf[1] = a.y; kf[2] = b.x; kf[3] = b.y;
    hf[0] = c.x; hf[1] = c.y; hf[2] = d.x; hf[3] = d.y;
}

__global__ __launch_bounds__(256) void fused_attn_kernel(float* __restrict__ out)
{
    int gw = (blockIdx.x * blockDim.x + threadIdx.x) >> 5;   // node id
    if (gw >= N_NODES) return;
    int lane = threadIdx.x & 31;
    int t = lane & 7;          // position within 8-lane group
    int g = lane >> 3;         // group 0..3 (edge within batch)

    int beg = g_rowStart[gw];
    int end = g_rowStart[gw + 1];

    // this lane writes dims [16t+4g .. 16t+4g+3]; 32 lanes cover all 128
    float* owr = out + (unsigned)(gw * F + 16 * t + 4 * g);

    if (beg == end) {
        *(float4*)owr = make_float4(0.f, 0.f, 0.f, 0.f);
        return;
    }

    // q for this lane's 16 dims
    float qf[16];
    {
        const float4* qp = (const float4*)(g_Q + (unsigned)(gw * F + 16 * t));
#pragma unroll
        for (int i = 0; i < 4; i++) {
            float4 v = qp[i];
            qf[4*i] = v.x; qf[4*i+1] = v.y; qf[4*i+2] = v.z; qf[4*i+3] = v.w;
        }
    }

    float acc[16];
#pragma unroll
    for (int i = 0; i < 16; i++) acc[i] = 0.f;
    float den = 0.f;
    const unsigned lb = (unsigned)(t << 6);   // t*64 byte base within row

    for (int chunk = beg; chunk < end; chunk += 32) {
        int idx = chunk + lane;
        int myO = (idx < end) ? __ldg(&g_srcOff[idx]) : 0;
        int m = end - chunk; if (m > 32) m = 32;

        for (int j = 0; j < m; j += 4) {
            int eidx = j + g;
            unsigned o = (unsigned)__shfl_sync(0xFFFFFFFFu, myO, eidx & 31) + lb;
            const char* p = (const char*)g_KH + o;
            uint4 r0 = *(const uint4*)(p);
            uint4 r1 = *(const uint4*)(p + 16);
            uint4 r2 = *(const uint4*)(p + 32);
            uint4 r3 = *(const uint4*)(p + 48);

            float kf[16], hf[16];
            unp(r0, kf + 0,  hf + 0);
            unp(r1, kf + 4,  hf + 4);
            unp(r2, kf + 8,  hf + 8);
            unp(r3, kf + 12, hf + 12);

            float v = 0.f;
#pragma unroll
            for (int i = 0; i < 16; i++) v = fmaf(qf[i], kf[i], v);
            v += __shfl_xor_sync(0xFFFFFFFFu, v, 4);
            v += __shfl_xor_sync(0xFFFFFFFFu, v, 2);
            v += __shfl_xor_sync(0xFFFFFFFFu, v, 1);

            float e = (eidx < m) ? __expf(v) : 0.f;
            den += e;
#pragma unroll
            for (int i = 0; i < 16; i++) acc[i] = fmaf(e, hf[i], acc[i]);
        }
    }

    // cross-group combine (once per node)
#pragma unroll
    for (int i = 0; i < 16; i++) {
        acc[i] += __shfl_xor_sync(0xFFFFFFFFu, acc[i], 8);
        acc[i] += __shfl_xor_sync(0xFFFFFFFFu, acc[i], 16);
    }
    den += __shfl_xor_sync(0xFFFFFFFFu, den, 8);
    den += __shfl_xor_sync(0xFFFFFFFFu, den, 16);

    float inv = 1.0f / den;
    *(float4*)owr = make_float4(acc[4*g] * inv, acc[4*g+1] * inv,
                                acc[4*g+2] * inv, acc[4*g+3] * inv);
}

// ---------------------------------------------------------------------------
// Inputs: 0 feat, 1 loc, 2 W_fc, 3 Wq, 4 Wk, 5 Wq2, 6 Wk2, 7 G_w, 8 embed,
// 9 boundaries, 10 src, 11 dst, 12 inter_ids  (e2 branch is dead code)
// ---------------------------------------------------------------------------
extern "C" void kernel_launch(void* const* d_in, const int* in_sizes, int n_in,
                              void* d_out, int out_size)
{
    const float* feat = (const float*)d_in[0];
    const float* Wfc  = (const float*)d_in[2];
    const float* Wq   = (const float*)d_in[3];
    const float* Wk   = (const float*)d_in[4];
    const int*   src  = (const int*)d_in[10];
    const int*   dst  = (const int*)d_in[11];
    float* out = (float*)d_out;

    static cudaStream_t s2 = nullptr;
    static cudaEvent_t evFork = nullptr, evJoin = nullptr;
    if (!s2) {
        cudaFuncSetAttribute(gemm3_tf32_kernel,
                             cudaFuncAttributeMaxDynamicSharedMemorySize,
                             SMEM_BYTES);
        cudaStreamCreateWithFlags(&s2, cudaStreamNonBlocking);
        cudaEventCreateWithFlags(&evFork, cudaEventDisableTiming);
        cudaEventCreateWithFlags(&evJoin, cudaEventDisableTiming);
    }

    // fork: CSR build on s2, GEMM on the main (capture) stream
    cudaEventRecord(evFork, 0);
    cudaStreamWaitEvent(s2, evFork, 0);

    {   // --- s2: CSR build (rank-based, atomic-free scatter) ---
        int t4 = (N_EDGES + 3) / 4;
        hist_kernel<<<(t4 + 255) / 256, 256, 0, s2>>>(dst);
        scan1_kernel<<<NBLK, 256, 0, s2>>>();
        scan23_kernel<<<NBLK, 256, 0, s2>>>();
        scatter_kernel<<<(t4 + 255) / 256, 256, 0, s2>>>(src, dst);
        cudaEventRecord(evJoin, s2);
    }

    // --- main stream: H, Q, K GEMMs ---
    gemm3_tf32_kernel<<<(N_NODES + 127) / 128, 256, SMEM_BYTES>>>(
        feat, Wfc, Wq, Wk);

    // join, then fused attention (1 warp per node, 8 lanes per edge)
    cudaStreamWaitEvent(0, evJoin, 0);
    fused_attn_kernel<<<(N_NODES * 32 + 255) / 256, 256>>>(out);
}

// round 13
// speedup vs baseline: 1.0587x; 1.0587x over previous
#include <cuda_runtime.h>
#include <cuda_fp16.h>
#include <cstdint>

#define N_NODES 40000
#define N_EDGES 640000
#define F 128
#define SCALE_INV 0.08838834764831845f   // 1/sqrt(128)

#define NBLK 157            // ceil(40000/256) scan blocks

#define LDA 132
#define LDB 136
#define SMEM_BYTES ((128 * LDA + 128 * LDB) * 4)   // 137216 B

// ---- static scratch ----
// Interleaved K/H (fp16): per node, 32 groups of 8 halves (512 B per node):
//   [g*8+0..3] = K cols 4g..4g+3,  [g*8+4..7] = H cols 4g..4g+3
__device__ __half g_KH[N_NODES * 2 * F];
__device__ float  g_Q [N_NODES * F];     // (feat @ Wq) * (1/sqrt(F))  fp32
__device__ int    g_deg[N_NODES];        // stays zero between invocations
__device__ int    g_rowStart[N_NODES + 1];
__device__ int    g_rank[N_EDGES];       // edge's rank within its dst node
__device__ int    g_srcOff[N_EDGES];     // src node id << 9 (BYTE offset in g_KH)
__device__ int    g_bsum[NBLK];

// ---------------------------------------------------------------------------
// hist: count degrees AND record each edge's arrival rank. 2 edges/thread.
__global__ void hist_kernel(const int* __restrict__ dst) {
    int base = (blockIdx.x * blockDim.x + threadIdx.x) << 1;
    if (base + 1 < N_EDGES) {
        int2 d = *(const int2*)(dst + base);
        int2 r;
        r.x = atomicAdd(&g_deg[d.x], 1);
        r.y = atomicAdd(&g_deg[d.y], 1);
        *(int2*)(g_rank + base) = r;
    } else if (base < N_EDGES) {
        g_rank[base] = atomicAdd(&g_deg[__ldg(&dst[base])], 1);
    }
}

// block-local exclusive scan of deg -> rowStart(local), block totals -> bsum.
// Zeroes g_deg after reading (invariant for next invocation).
__global__ __launch_bounds__(256) void scan1_kernel() {
    __shared__ int s[256];
    int tid = threadIdx.x;
    int i = blockIdx.x * 256 + tid;
    int v = 0;
    if (i < N_NODES) { v = g_deg[i]; g_deg[i] = 0; }
    s[tid] = v;
    __syncthreads();
#pragma unroll
    for (int off = 1; off < 256; off <<= 1) {
        int t = (tid >= off) ? s[tid - off] : 0;
        __syncthreads();
        s[tid] += t;
        __syncthreads();
    }
    if (i < N_NODES) g_rowStart[i] = s[tid] - v;
    if (tid == 255) g_bsum[blockIdx.x] = s[255];
}

// add block offsets (each block reduces bsum[t < blockIdx] itself); sentinel.
__global__ __launch_bounds__(256) void scan23_kernel() {
    __shared__ int red[256];
    int tid = threadIdx.x;
    int v = (tid < NBLK && tid < blockIdx.x) ? g_bsum[tid] : 0;
    red[tid] = v;
    __syncthreads();
#pragma unroll
    for (int off = 128; off > 0; off >>= 1) {
        if (tid < off) red[tid] += red[tid + off];
        __syncthreads();
    }
    int offset = red[0];

    int i = blockIdx.x * 256 + tid;
    if (i < N_NODES) g_rowStart[i] += offset;
    if (i == 0) g_rowStart[N_NODES] = N_EDGES;
}

// atomic-free scatter: slot = rowStart[dst] + rank[edge]. 2 edges/thread.
__global__ void scatter_kernel(const int* __restrict__ src,
                               const int* __restrict__ dst) {
    int base = (blockIdx.x * blockDim.x + threadIdx.x) << 1;
    if (base + 1 < N_EDGES) {
        int2 d = *(const int2*)(dst + base);
        int2 s = *(const int2*)(src + base);
        int2 r = *(const int2*)(g_rank + base);
        g_srcOff[g_rowStart[d.x] + r.x] = s.x << 9;
        g_srcOff[g_rowStart[d.y] + r.y] = s.y << 9;
    } else if (base < N_EDGES) {
        int d = __ldg(&dst[base]);
        g_srcOff[g_rowStart[d] + g_rank[base]] = __ldg(&src[base]) << 9;
    }
}

// ---------------------------------------------------------------------------
__device__ __forceinline__ uint32_t f2tf32(float x) {
    uint32_t r;
    asm("cvt.rna.tf32.f32 %0, %1;" : "=r"(r) : "f"(x));
    return r;
}

// Fused 3-way GEMM (tf32 tensor cores): one 128x128 row tile per CTA;
// A staged ONCE, the three weights staged sequentially into Bs.
// H (j=0) and K (j=2) write fp16 into the interleaved g_KH; Q (j=1) fp32,
// pre-scaled by 1/sqrt(F).
__global__ __launch_bounds__(256) void gemm3_tf32_kernel(
    const float* __restrict__ feat,
    const float* __restrict__ Wfc,
    const float* __restrict__ Wq,
    const float* __restrict__ Wk)
{
    extern __shared__ float sm[];
    float* As = sm;                 // [128][LDA]
    float* Bs = sm + 128 * LDA;     // [128][LDB]

    const int tid  = threadIdx.x;
    const int row0 = blockIdx.x * 128;

    for (int i = tid; i < 4096; i += 256) {
        int r = i >> 5, c4 = (i & 31) << 2;
        float4 v = make_float4(0.f, 0.f, 0.f, 0.f);
        if (row0 + r < N_NODES)
            v = *(const float4*)(feat + (size_t)(row0 + r) * F + c4);
        *(float4*)(As + r * LDA + c4) = v;
    }

    const int wid  = tid >> 5;
    const int lane = tid & 31;
    const int wm   = (wid & 3) << 5;
    const int wn   = (wid >> 2) << 6;
    const int grp  = lane >> 2;
    const int qid  = lane & 3;

    const float* Ws[3] = { Wfc, Wq, Wk };

#pragma unroll
    for (int j = 0; j < 3; j++) {
        __syncthreads();
        const float* W = Ws[j];
        for (int i = tid; i < 4096; i += 256) {
            int r = i >> 5, c4 = (i & 31) << 2;
            *(float4*)(Bs + r * LDB + c4) = *(const float4*)(W + r * F + c4);
        }
        __syncthreads();

        float acc[2][8][4];
#pragma unroll
        for (int mi = 0; mi < 2; mi++)
#pragma unroll
            for (int nt = 0; nt < 8; nt++)
#pragma unroll
                for (int c = 0; c < 4; c++) acc[mi][nt][c] = 0.0f;

#pragma unroll
        for (int ks = 0; ks < 16; ks++) {
            const int k0 = ks << 3;
            uint32_t a[2][4];
#pragma unroll
            for (int mi = 0; mi < 2; mi++) {
                const int rb = wm + (mi << 4);
                a[mi][0] = f2tf32(As[(rb + grp)     * LDA + k0 + qid]);
                a[mi][1] = f2tf32(As[(rb + grp + 8) * LDA + k0 + qid]);
                a[mi][2] = f2tf32(As[(rb + grp)     * LDA + k0 + qid + 4]);
                a[mi][3] = f2tf32(As[(rb + grp + 8) * LDA + k0 + qid + 4]);
            }
#pragma unroll
            for (int nt = 0; nt < 8; nt++) {
                const int n0 = wn + (nt << 3);
                uint32_t b0 = f2tf32(Bs[(k0 + qid)     * LDB + n0 + grp]);
                uint32_t b1 = f2tf32(Bs[(k0 + qid + 4) * LDB + n0 + grp]);
#pragma unroll
                for (int mi = 0; mi < 2; mi++) {
                    asm volatile(
                        "mma.sync.aligned.m16n8k8.row.col.f32.tf32.tf32.f32 "
                        "{%0,%1,%2,%3}, {%4,%5,%6,%7}, {%8,%9}, {%0,%1,%2,%3};"
                        : "+f"(acc[mi][nt][0]), "+f"(acc[mi][nt][1]),
                          "+f"(acc[mi][nt][2]), "+f"(acc[mi][nt][3])
                        : "r"(a[mi][0]), "r"(a[mi][1]), "r"(a[mi][2]),
                          "r"(a[mi][3]), "r"(b0), "r"(b1));
                }
            }
        }

        const int khOff = (j == 0) ? 4 : 0;   // H -> slot+4, K -> slot+0
#pragma unroll
        for (int mi = 0; mi < 2; mi++) {
            const int r = row0 + wm + (mi << 4) + grp;
#pragma unroll
            for (int nt = 0; nt < 8; nt++) {
                const int col = wn + (nt << 3) + (qid << 1);   // col even
                if (j == 1) {          // Q fp32, pre-scaled
                    if (r < N_NODES)
                        *(float2*)(g_Q + (size_t)r * F + col) =
                            make_float2(acc[mi][nt][0] * SCALE_INV,
                                        acc[mi][nt][1] * SCALE_INV);
                    if (r + 8 < N_NODES)
                        *(float2*)(g_Q + (size_t)(r + 8) * F + col) =
                            make_float2(acc[mi][nt][2] * SCALE_INV,
                                        acc[mi][nt][3] * SCALE_INV);
                } else {               // H/K fp16 interleaved
                    const int slot = ((col >> 2) << 3) + khOff + (col & 3);
                    if (r < N_NODES)
                        *(__half2*)(g_KH + (size_t)r * 256 + slot) =
                            __floats2half2_rn(acc[mi][nt][0], acc[mi][nt][1]);
                    if (r + 8 < N_NODES)
                        *(__half2*)(g_KH + (size_t)(r + 8) * 256 + slot) =
                            __floats2half2_rn(acc[mi][nt][2], acc[mi][nt][3]);
                }
            }
        }
    }
}

// ---------------------------------------------------------------------------
// Fused attention: ONE warp per dst node (R9 layout), ILP-4 batches with
// partitioned warp reduction + DOUBLE-BUFFERED batch loads (8 LDG.128 in
// flight per warp).
// ---------------------------------------------------------------------------
__global__ __launch_bounds__(256) void fused_attn_kernel(float* __restrict__ out)
{
    int gw = (blockIdx.x * blockDim.x + threadIdx.x) >> 5;   // node id
    if (gw >= N_NODES) return;
    int lane = threadIdx.x & 31;

    int beg = g_rowStart[gw];
    int end = g_rowStart[gw + 1];

    float* orow = out + (size_t)gw * F + lane * 4;
    if (beg == end) {
        *(float4*)orow = make_float4(0.f, 0.f, 0.f, 0.f);
        return;
    }

    float4 q = *(const float4*)(g_Q + (unsigned)(gw * F + lane * 4));

    float ax = 0.f, ay = 0.f, az = 0.f, aw = 0.f;
    float den = 0.f;
    const unsigned lo = (unsigned)(lane << 4);   // byte offset in row
    const int g = lane >> 3;                     // lane group 0..3
    const char* base = (const char*)g_KH;

    for (int chunk = beg; chunk < end; chunk += 32) {
        int idx = chunk + lane;
        int myO = (idx < end) ? __ldg(&g_srcOff[idx]) : 0;
        int m = end - chunk; if (m > 32) m = 32;

        int j = 0;
        if (j + 4 <= m) {
            // preload batch 0
            uint4 c0, c1, c2, c3;
            {
                unsigned o0 = (unsigned)__shfl_sync(0xFFFFFFFFu, myO, 0) + lo;
                unsigned o1 = (unsigned)__shfl_sync(0xFFFFFFFFu, myO, 1) + lo;
                unsigned o2 = (unsigned)__shfl_sync(0xFFFFFFFFu, myO, 2) + lo;
                unsigned o3 = (unsigned)__shfl_sync(0xFFFFFFFFu, myO, 3) + lo;
                c0 = *(const uint4*)(base + o0);
                c1 = *(const uint4*)(base + o1);
                c2 = *(const uint4*)(base + o2);
                c3 = *(const uint4*)(base + o3);
            }
            for (; j + 4 <= m; j += 4) {
                uint4 n0, n1, n2, n3;
                const bool more = (j + 8 <= m);
                if (more) {
                    unsigned o0 = (unsigned)__shfl_sync(0xFFFFFFFFu, myO, j + 4) + lo;
                    unsigned o1 = (unsigned)__shfl_sync(0xFFFFFFFFu, myO, j + 5) + lo;
                    unsigned o2 = (unsigned)__shfl_sync(0xFFFFFFFFu, myO, j + 6) + lo;
                    unsigned o3 = (unsigned)__shfl_sync(0xFFFFFFFFu, myO, j + 7) + lo;
                    n0 = *(const uint4*)(base + o0);
                    n1 = *(const uint4*)(base + o1);
                    n2 = *(const uint4*)(base + o2);
                    n3 = *(const uint4*)(base + o3);
                }

                // unpack current batch
                float2 k0a = __half22float2(*(__half2*)&c0.x);
                float2 k0b = __half22float2(*(__half2*)&c0.y);
                float2 h0a = __half22float2(*(__half2*)&c0.z);
                float2 h0b = __half22float2(*(__half2*)&c0.w);
                float2 k1a = __half22float2(*(__half2*)&c1.x);
                float2 k1b = __half22float2(*(__half2*)&c1.y);
                float2 h1a = __half22float2(*(__half2*)&c1.z);
                float2 h1b = __half22float2(*(__half2*)&c1.w);
                float2 k2a = __half22float2(*(__half2*)&c2.x);
                float2 k2b = __half22float2(*(__half2*)&c2.y);
                float2 h2a = __half22float2(*(__half2*)&c2.z);
                float2 h2b = __half22float2(*(__half2*)&c2.w);
                float2 k3a = __half22float2(*(__half2*)&c3.x);
                float2 k3b = __half22float2(*(__half2*)&c3.y);
                float2 h3a = __half22float2(*(__half2*)&c3.z);
                float2 h3b = __half22float2(*(__half2*)&c3.w);

                float v0 = q.x*k0a.x + q.y*k0a.y + q.z*k0b.x + q.w*k0b.y;
                float v1 = q.x*k1a.x + q.y*k1a.y + q.z*k1b.x + q.w*k1b.y;
                float v2 = q.x*k2a.x + q.y*k2a.y + q.z*k2b.x + q.w*k2b.y;
                float v3 = q.x*k3a.x + q.y*k3a.y + q.z*k3b.x + q.w*k3b.y;

                // partitioned reduction: levels 16,8 on all four
                v0 += __shfl_xor_sync(0xFFFFFFFFu, v0, 16);
                v1 += __shfl_xor_sync(0xFFFFFFFFu, v1, 16);
                v2 += __shfl_xor_sync(0xFFFFFFFFu, v2, 16);
                v3 += __shfl_xor_sync(0xFFFFFFFFu, v3, 16);
                v0 += __shfl_xor_sync(0xFFFFFFFFu, v0, 8);
                v1 += __shfl_xor_sync(0xFFFFFFFFu, v1, 8);
                v2 += __shfl_xor_sync(0xFFFFFFFFu, v2, 8);
                v3 += __shfl_xor_sync(0xFFFFFFFFu, v3, 8);
                float x = v0;
                x = (g == 1) ? v1 : x;
                x = (g == 2) ? v2 : x;
                x = (g == 3) ? v3 : x;
                x += __shfl_xor_sync(0xFFFFFFFFu, x, 4);
                x += __shfl_xor_sync(0xFFFFFFFFu, x, 2);
                x += __shfl_xor_sync(0xFFFFFFFFu, x, 1);
                float y = __expf(x);                     // ONE exp per lane
                float e0 = __shfl_sync(0xFFFFFFFFu, y, 0);
                float e1 = __shfl_sync(0xFFFFFFFFu, y, 8);
                float e2 = __shfl_sync(0xFFFFFFFFu, y, 16);
                float e3 = __shfl_sync(0xFFFFFFFFu, y, 24);

                den += (e0 + e1) + (e2 + e3);
                ax += e0*h0a.x + e1*h1a.x + e2*h2a.x + e3*h3a.x;
                ay += e0*h0a.y + e1*h1a.y + e2*h2a.y + e3*h3a.y;
                az += e0*h0b.x + e1*h1b.x + e2*h2b.x + e3*h3b.x;
                aw += e0*h0b.y + e1*h1b.y + e2*h2b.y + e3*h3b.y;

                if (more) { c0 = n0; c1 = n1; c2 = n2; c3 = n3; }
            }
        }
        for (; j < m; j++) {
            unsigned o0 = (unsigned)__shfl_sync(0xFFFFFFFFu, myO, j) + lo;
            uint4 raw = *(const uint4*)(base + o0);
            float2 ka = __half22float2(*(__half2*)&raw.x);
            float2 kb = __half22float2(*(__half2*)&raw.y);
            float2 ha = __half22float2(*(__half2*)&raw.z);
            float2 hb = __half22float2(*(__half2*)&raw.w);
            float v0 = q.x*ka.x + q.y*ka.y + q.z*kb.x + q.w*kb.y;
#pragma unroll
            for (int o = 16; o > 0; o >>= 1)
                v0 += __shfl_xor_sync(0xFFFFFFFFu, v0, o);
            float e0 = __expf(v0);
            den += e0;
            ax += e0*ha.x; ay += e0*ha.y; az += e0*hb.x; aw += e0*hb.y;
        }
    }

    float inv = 1.0f / den;
    *(float4*)orow = make_float4(ax * inv, ay * inv, az * inv, aw * inv);
}

// ---------------------------------------------------------------------------
// Inputs: 0 feat, 1 loc, 2 W_fc, 3 Wq, 4 Wk, 5 Wq2, 6 Wk2, 7 G_w, 8 embed,
// 9 boundaries, 10 src, 11 dst, 12 inter_ids  (e2 branch is dead code)
// ---------------------------------------------------------------------------
extern "C" void kernel_launch(void* const* d_in, const int* in_sizes, int n_in,
                              void* d_out, int out_size)
{
    const float* feat = (const float*)d_in[0];
    const float* Wfc  = (const float*)d_in[2];
    const float* Wq   = (const float*)d_in[3];
    const float* Wk   = (const float*)d_in[4];
    const int*   src  = (const int*)d_in[10];
    const int*   dst  = (const int*)d_in[11];
    float* out = (float*)d_out;

    static cudaStream_t s2 = nullptr;
    static cudaEvent_t evFork = nullptr, evJoin = nullptr;
    if (!s2) {
        cudaFuncSetAttribute(gemm3_tf32_kernel,
                             cudaFuncAttributeMaxDynamicSharedMemorySize,
                             SMEM_BYTES);
        cudaStreamCreateWithFlags(&s2, cudaStreamNonBlocking);
        cudaEventCreateWithFlags(&evFork, cudaEventDisableTiming);
        cudaEventCreateWithFlags(&evJoin, cudaEventDisableTiming);
    }

    // fork: CSR build on s2, GEMM on the main (capture) stream
    cudaEventRecord(evFork, 0);
    cudaStreamWaitEvent(s2, evFork, 0);

    {   // --- s2: CSR build (rank-based, atomic-free scatter) ---
        int t2 = (N_EDGES + 1) / 2;
        hist_kernel<<<(t2 + 255) / 256, 256, 0, s2>>>(dst);
        scan1_kernel<<<NBLK, 256, 0, s2>>>();
        scan23_kernel<<<NBLK, 256, 0, s2>>>();
        scatter_kernel<<<(t2 + 255) / 256, 256, 0, s2>>>(src, dst);
        cudaEventRecord(evJoin, s2);
    }

    // --- main stream: H, Q, K GEMMs ---
    gemm3_tf32_kernel<<<(N_NODES + 127) / 128, 256, SMEM_BYTES>>>(
        feat, Wfc, Wq, Wk);

    // join, then fused attention (1 warp per node, double-buffered)
    cudaStreamWaitEvent(0, evJoin, 0);
    fused_attn_kernel<<<(N_NODES * 32 + 255) / 256, 256>>>(out);
}

// round 14
// speedup vs baseline: 1.2392x; 1.1706x over previous
#include <cuda_runtime.h>
#include <cuda_fp16.h>
#include <cstdint>

#define N_NODES 40000
#define N_EDGES 640000
#define F 128
#define SCALE_INV 0.08838834764831845f   // 1/sqrt(128)

#define NBLK 157            // ceil(40000/256) scan blocks

#define LDA 132
#define LDB 136
#define SMEM_BYTES ((128 * LDA + 128 * LDB) * 4)   // 137216 B

#define ATTN_BLOCKS 592     // 4 blocks/SM x 148 SMs
#define ATTN_WARPS (ATTN_BLOCKS * 8)

// ---- static scratch ----
// Interleaved K/H (fp16): per node, 32 groups of 8 halves (512 B per node):
//   [g*8+0..3] = K cols 4g..4g+3,  [g*8+4..7] = H cols 4g..4g+3
__device__ __half g_KH[N_NODES * 2 * F];
__device__ float  g_Q [N_NODES * F];     // (feat @ Wq) * (1/sqrt(F))  fp32
__device__ int    g_deg[N_NODES];        // stays zero between invocations
__device__ int    g_rowStart[N_NODES + 1];
__device__ int    g_rank[N_EDGES];       // edge's rank within its dst node
__device__ int    g_srcOff[N_EDGES];     // src node id << 9 (BYTE offset in g_KH)
__device__ int    g_bsum[NBLK];

// ---------------------------------------------------------------------------
// hist: count degrees AND record each edge's arrival rank (atomicAdd return).
__global__ void hist_kernel(const int* __restrict__ dst) {
    int base = (blockIdx.x * blockDim.x + threadIdx.x) << 2;   // 4 edges/thread
    if (base + 3 < N_EDGES) {
        int4 d = *(const int4*)(dst + base);
        int4 r;
        r.x = atomicAdd(&g_deg[d.x], 1);
        r.y = atomicAdd(&g_deg[d.y], 1);
        r.z = atomicAdd(&g_deg[d.z], 1);
        r.w = atomicAdd(&g_deg[d.w], 1);
        *(int4*)(g_rank + base) = r;
    } else {
        for (int e = base; e < N_EDGES; e++)
            g_rank[e] = atomicAdd(&g_deg[__ldg(&dst[e])], 1);
    }
}

// block-local exclusive scan of deg -> rowStart(local), block totals -> bsum.
// Zeroes g_deg after reading (invariant for next invocation).
__global__ __launch_bounds__(256) void scan1_kernel() {
    __shared__ int s[256];
    int tid = threadIdx.x;
    int i = blockIdx.x * 256 + tid;
    int v = 0;
    if (i < N_NODES) { v = g_deg[i]; g_deg[i] = 0; }
    s[tid] = v;
    __syncthreads();
#pragma unroll
    for (int off = 1; off < 256; off <<= 1) {
        int t = (tid >= off) ? s[tid - off] : 0;
        __syncthreads();
        s[tid] += t;
        __syncthreads();
    }
    if (i < N_NODES) g_rowStart[i] = s[tid] - v;
    if (tid == 255) g_bsum[blockIdx.x] = s[255];
}

// add block offsets (each block reduces bsum[t < blockIdx] itself); sentinel.
__global__ __launch_bounds__(256) void scan23_kernel() {
    __shared__ int red[256];
    int tid = threadIdx.x;
    int v = (tid < NBLK && tid < blockIdx.x) ? g_bsum[tid] : 0;
    red[tid] = v;
    __syncthreads();
#pragma unroll
    for (int off = 128; off > 0; off >>= 1) {
        if (tid < off) red[tid] += red[tid + off];
        __syncthreads();
    }
    int offset = red[0];

    int i = blockIdx.x * 256 + tid;
    if (i < N_NODES) g_rowStart[i] += offset;
    if (i == 0) g_rowStart[N_NODES] = N_EDGES;
}

// atomic-free scatter: slot = rowStart[dst] + rank[edge]
__global__ void scatter_kernel(const int* __restrict__ src,
                               const int* __restrict__ dst) {
    int base = (blockIdx.x * blockDim.x + threadIdx.x) << 2;   // 4 edges/thread
    if (base + 3 < N_EDGES) {
        int4 d = *(const int4*)(dst + base);
        int4 s = *(const int4*)(src + base);
        int4 r = *(const int4*)(g_rank + base);
        g_srcOff[g_rowStart[d.x] + r.x] = s.x << 9;
        g_srcOff[g_rowStart[d.y] + r.y] = s.y << 9;
        g_srcOff[g_rowStart[d.z] + r.z] = s.z << 9;
        g_srcOff[g_rowStart[d.w] + r.w] = s.w << 9;
    } else {
        for (int e = base; e < N_EDGES; e++) {
            int d = __ldg(&dst[e]);
            g_srcOff[g_rowStart[d] + g_rank[e]] = __ldg(&src[e]) << 9;
        }
    }
}

// ---------------------------------------------------------------------------
__device__ __forceinline__ uint32_t f2tf32(float x) {
    uint32_t r;
    asm("cvt.rna.tf32.f32 %0, %1;" : "=r"(r) : "f"(x));
    return r;
}

// Fused 3-way GEMM (tf32 tensor cores): one 128x128 row tile per CTA;
// A staged ONCE, the three weights staged sequentially into Bs.
// H (j=0) and K (j=2) write fp16 into the interleaved g_KH; Q (j=1) fp32,
// pre-scaled by 1/sqrt(F).
__global__ __launch_bounds__(256) void gemm3_tf32_kernel(
    const float* __restrict__ feat,
    const float* __restrict__ Wfc,
    const float* __restrict__ Wq,
    const float* __restrict__ Wk)
{
    extern __shared__ float sm[];
    float* As = sm;                 // [128][LDA]
    float* Bs = sm + 128 * LDA;     // [128][LDB]

    const int tid  = threadIdx.x;
    const int row0 = blockIdx.x * 128;

    for (int i = tid; i < 4096; i += 256) {
        int r = i >> 5, c4 = (i & 31) << 2;
        float4 v = make_float4(0.f, 0.f, 0.f, 0.f);
        if (row0 + r < N_NODES)
            v = *(const float4*)(feat + (size_t)(row0 + r) * F + c4);
        *(float4*)(As + r * LDA + c4) = v;
    }

    const int wid  = tid >> 5;
    const int lane = tid & 31;
    const int wm   = (wid & 3) << 5;
    const int wn   = (wid >> 2) << 6;
    const int grp  = lane >> 2;
    const int qid  = lane & 3;

    const float* Ws[3] = { Wfc, Wq, Wk };

#pragma unroll
    for (int j = 0; j < 3; j++) {
        __syncthreads();
        const float* W = Ws[j];
        for (int i = tid; i < 4096; i += 256) {
            int r = i >> 5, c4 = (i & 31) << 2;
            *(float4*)(Bs + r * LDB + c4) = *(const float4*)(W + r * F + c4);
        }
        __syncthreads();

        float acc[2][8][4];
#pragma unroll
        for (int mi = 0; mi < 2; mi++)
#pragma unroll
            for (int nt = 0; nt < 8; nt++)
#pragma unroll
                for (int c = 0; c < 4; c++) acc[mi][nt][c] = 0.0f;

#pragma unroll
        for (int ks = 0; ks < 16; ks++) {
            const int k0 = ks << 3;
            uint32_t a[2][4];
#pragma unroll
            for (int mi = 0; mi < 2; mi++) {
                const int rb = wm + (mi << 4);
                a[mi][0] = f2tf32(As[(rb + grp)     * LDA + k0 + qid]);
                a[mi][1] = f2tf32(As[(rb + grp + 8) * LDA + k0 + qid]);
                a[mi][2] = f2tf32(As[(rb + grp)     * LDA + k0 + qid + 4]);
                a[mi][3] = f2tf32(As[(rb + grp + 8) * LDA + k0 + qid + 4]);
            }
#pragma unroll
            for (int nt = 0; nt < 8; nt++) {
                const int n0 = wn + (nt << 3);
                uint32_t b0 = f2tf32(Bs[(k0 + qid)     * LDB + n0 + grp]);
                uint32_t b1 = f2tf32(Bs[(k0 + qid + 4) * LDB + n0 + grp]);
#pragma unroll
                for (int mi = 0; mi < 2; mi++) {
                    asm volatile(
                        "mma.sync.aligned.m16n8k8.row.col.f32.tf32.tf32.f32 "
                        "{%0,%1,%2,%3}, {%4,%5,%6,%7}, {%8,%9}, {%0,%1,%2,%3};"
                        : "+f"(acc[mi][nt][0]), "+f"(acc[mi][nt][1]),
                          "+f"(acc[mi][nt][2]), "+f"(acc[mi][nt][3])
                        : "r"(a[mi][0]), "r"(a[mi][1]), "r"(a[mi][2]),
                          "r"(a[mi][3]), "r"(b0), "r"(b1));
                }
            }
        }

        const int khOff = (j == 0) ? 4 : 0;   // H -> slot+4, K -> slot+0
#pragma unroll
        for (int mi = 0; mi < 2; mi++) {
            const int r = row0 + wm + (mi << 4) + grp;
#pragma unroll
            for (int nt = 0; nt < 8; nt++) {
                const int col = wn + (nt << 3) + (qid << 1);   // col even
                if (j == 1) {          // Q fp32, pre-scaled
                    if (r < N_NODES)
                        *(float2*)(g_Q + (size_t)r * F + col) =
                            make_float2(acc[mi][nt][0] * SCALE_INV,
                                        acc[mi][nt][1] * SCALE_INV);
                    if (r + 8 < N_NODES)
                        *(float2*)(g_Q + (size_t)(r + 8) * F + col) =
                            make_float2(acc[mi][nt][2] * SCALE_INV,
                                        acc[mi][nt][3] * SCALE_INV);
                } else {               // H/K fp16 interleaved
                    const int slot = ((col >> 2) << 3) + khOff + (col & 3);
                    if (r < N_NODES)
                        *(__half2*)(g_KH + (size_t)r * 256 + slot) =
                            __floats2half2_rn(acc[mi][nt][0], acc[mi][nt][1]);
                    if (r + 8 < N_NODES)
                        *(__half2*)(g_KH + (size_t)(r + 8) * 256 + slot) =
                            __floats2half2_rn(acc[mi][nt][2], acc[mi][nt][3]);
                }
            }
        }
    }
}

// ---------------------------------------------------------------------------
// Fused attention: PERSISTENT WARPS — each warp strides over nodes
// (gw += ATTN_WARPS), inner body identical to the measured-best R9 layout
// (32 lanes per edge, ILP-4, partitioned reduction, one exp per lane).
// Removes block-retirement tails from degree variance.
// ---------------------------------------------------------------------------
__device__ __forceinline__ void load_kh(unsigned off,
    float& kx, float& ky, float& kz, float& kw,
    float& hx, float& hy, float& hz, float& hw)
{
    uint4 raw = *(const uint4*)((const char*)g_KH + off);
    float2 f0 = __half22float2(*(__half2*)&raw.x);
    float2 f1 = __half22float2(*(__half2*)&raw.y);
    float2 f2 = __half22float2(*(__half2*)&raw.z);
    float2 f3 = __half22float2(*(__half2*)&raw.w);
    kx = f0.x; ky = f0.y; kz = f1.x; kw = f1.y;
    hx = f2.x; hy = f2.y; hz = f3.x; hw = f3.y;
}

__global__ __launch_bounds__(256) void fused_attn_kernel(float* __restrict__ out)
{
    const int warp0 = (blockIdx.x * blockDim.x + threadIdx.x) >> 5;
    const int lane  = threadIdx.x & 31;
    const unsigned lo = (unsigned)(lane << 4);   // byte offset within row
    const int g = lane >> 3;                     // lane group 0..3

    for (int gw = warp0; gw < N_NODES; gw += ATTN_WARPS) {
        int beg = g_rowStart[gw];
        int end = g_rowStart[gw + 1];

        float* orow = out + (size_t)gw * F + lane * 4;
        if (beg == end) {
            *(float4*)orow = make_float4(0.f, 0.f, 0.f, 0.f);
            continue;
        }

        float4 q = *(const float4*)(g_Q + (unsigned)(gw * F + lane * 4));

        float ax = 0.f, ay = 0.f, az = 0.f, aw = 0.f;
        float den = 0.f;

        for (int chunk = beg; chunk < end; chunk += 32) {
            int idx = chunk + lane;
            int myO = (idx < end) ? __ldg(&g_srcOff[idx]) : 0;
            int m = end - chunk; if (m > 32) m = 32;

            int j = 0;
            for (; j + 4 <= m; j += 4) {
                unsigned o0 = (unsigned)__shfl_sync(0xFFFFFFFFu, myO, j)     + lo;
                unsigned o1 = (unsigned)__shfl_sync(0xFFFFFFFFu, myO, j + 1) + lo;
                unsigned o2 = (unsigned)__shfl_sync(0xFFFFFFFFu, myO, j + 2) + lo;
                unsigned o3 = (unsigned)__shfl_sync(0xFFFFFFFFu, myO, j + 3) + lo;
                float k0x,k0y,k0z,k0w, h0x,h0y,h0z,h0w;
                float k1x,k1y,k1z,k1w, h1x,h1y,h1z,h1w;
                float k2x,k2y,k2z,k2w, h2x,h2y,h2z,h2w;
                float k3x,k3y,k3z,k3w, h3x,h3y,h3z,h3w;
                load_kh(o0, k0x,k0y,k0z,k0w, h0x,h0y,h0z,h0w);
                load_kh(o1, k1x,k1y,k1z,k1w, h1x,h1y,h1z,h1w);
                load_kh(o2, k2x,k2y,k2z,k2w, h2x,h2y,h2z,h2w);
                load_kh(o3, k3x,k3y,k3z,k3w, h3x,h3y,h3z,h3w);

                float v0 = q.x*k0x + q.y*k0y + q.z*k0z + q.w*k0w;
                float v1 = q.x*k1x + q.y*k1y + q.z*k1z + q.w*k1w;
                float v2 = q.x*k2x + q.y*k2y + q.z*k2z + q.w*k2w;
                float v3 = q.x*k3x + q.y*k3y + q.z*k3z + q.w*k3w;

                // partitioned reduction: levels 16,8 on all four
                v0 += __shfl_xor_sync(0xFFFFFFFFu, v0, 16);
                v1 += __shfl_xor_sync(0xFFFFFFFFu, v1, 16);
                v2 += __shfl_xor_sync(0xFFFFFFFFu, v2, 16);
                v3 += __shfl_xor_sync(0xFFFFFFFFu, v3, 16);
                v0 += __shfl_xor_sync(0xFFFFFFFFu, v0, 8);
                v1 += __shfl_xor_sync(0xFFFFFFFFu, v1, 8);
                v2 += __shfl_xor_sync(0xFFFFFFFFu, v2, 8);
                v3 += __shfl_xor_sync(0xFFFFFFFFu, v3, 8);
                // each 8-lane group takes one edge's partial (xor 4,2,1 in-group)
                float x = v0;
                x = (g == 1) ? v1 : x;
                x = (g == 2) ? v2 : x;
                x = (g == 3) ? v3 : x;
                x += __shfl_xor_sync(0xFFFFFFFFu, x, 4);
                x += __shfl_xor_sync(0xFFFFFFFFu, x, 2);
                x += __shfl_xor_sync(0xFFFFFFFFu, x, 1);
                float y = __expf(x);                     // ONE exp per lane
                float e0 = __shfl_sync(0xFFFFFFFFu, y, 0);
                float e1 = __shfl_sync(0xFFFFFFFFu, y, 8);
                float e2 = __shfl_sync(0xFFFFFFFFu, y, 16);
                float e3 = __shfl_sync(0xFFFFFFFFu, y, 24);

                den += (e0 + e1) + (e2 + e3);
                ax += e0*h0x + e1*h1x + e2*h2x + e3*h3x;
                ay += e0*h0y + e1*h1y + e2*h2y + e3*h3y;
                az += e0*h0z + e1*h1z + e2*h2z + e3*h3z;
                aw += e0*h0w + e1*h1w + e2*h2w + e3*h3w;
            }
            for (; j < m; j++) {
                unsigned o0 = (unsigned)__shfl_sync(0xFFFFFFFFu, myO, j) + lo;
                float kx,ky,kz,kw, hx,hy,hz,hw;
                load_kh(o0, kx,ky,kz,kw, hx,hy,hz,hw);
                float v0 = q.x*kx + q.y*ky + q.z*kz + q.w*kw;
#pragma unroll
                for (int o = 16; o > 0; o >>= 1)
                    v0 += __shfl_xor_sync(0xFFFFFFFFu, v0, o);
                float e0 = __expf(v0);
                den += e0;
                ax += e0*hx; ay += e0*hy; az += e0*hz; aw += e0*hw;
            }
        }

        float inv = 1.0f / den;
        *(float4*)orow = make_float4(ax * inv, ay * inv, az * inv, aw * inv);
    }
}

// ---------------------------------------------------------------------------
// Inputs: 0 feat, 1 loc, 2 W_fc, 3 Wq, 4 Wk, 5 Wq2, 6 Wk2, 7 G_w, 8 embed,
// 9 boundaries, 10 src, 11 dst, 12 inter_ids  (e2 branch is dead code)
// ---------------------------------------------------------------------------
extern "C" void kernel_launch(void* const* d_in, const int* in_sizes, int n_in,
                              void* d_out, int out_size)
{
    const float* feat = (const float*)d_in[0];
    const float* Wfc  = (const float*)d_in[2];
    const float* Wq   = (const float*)d_in[3];
    const float* Wk   = (const float*)d_in[4];
    const int*   src  = (const int*)d_in[10];
    const int*   dst  = (const int*)d_in[11];
    float* out = (float*)d_out;

    static cudaStream_t s2 = nullptr;
    static cudaEvent_t evFork = nullptr, evJoin = nullptr;
    if (!s2) {
        cudaFuncSetAttribute(gemm3_tf32_kernel,
                             cudaFuncAttributeMaxDynamicSharedMemorySize,
                             SMEM_BYTES);
        cudaStreamCreateWithFlags(&s2, cudaStreamNonBlocking);
        cudaEventCreateWithFlags(&evFork, cudaEventDisableTiming);
        cudaEventCreateWithFlags(&evJoin, cudaEventDisableTiming);
    }

    // fork: CSR build on s2, GEMM on the main (capture) stream
    cudaEventRecord(evFork, 0);
    cudaStreamWaitEvent(s2, evFork, 0);

    {   // --- s2: CSR build (rank-based, atomic-free scatter) ---
        int t4 = (N_EDGES + 3) / 4;
        hist_kernel<<<(t4 + 255) / 256, 256, 0, s2>>>(dst);
        scan1_kernel<<<NBLK, 256, 0, s2>>>();
        scan23_kernel<<<NBLK, 256, 0, s2>>>();
        scatter_kernel<<<(t4 + 255) / 256, 256, 0, s2>>>(src, dst);
        cudaEventRecord(evJoin, s2);
    }

    // --- main stream: H, Q, K GEMMs ---
    gemm3_tf32_kernel<<<(N_NODES + 127) / 128, 256, SMEM_BYTES>>>(
        feat, Wfc, Wq, Wk);

    // join, then fused attention (persistent warps)
    cudaStreamWaitEvent(0, evJoin, 0);
    fused_attn_kernel<<<ATTN_BLOCKS, 256>>>(out);
}

// round 15
// speedup vs baseline: 1.3393x; 1.0807x over previous
#include <cuda_runtime.h>
#include <cuda_fp16.h>
#include <cstdint>

#define N_NODES 40000
#define N_EDGES 640000
#define F 128
#define SCALE_INV 0.08838834764831845f   // 1/sqrt(128)

#define NBLK 157            // ceil(40000/256) scan blocks

#define LDA 132
#define LDB 136
#define SMEM_BYTES ((128 * LDA + 128 * LDB) * 4)   // 137216 B

// ---- static scratch ----
// Interleaved K/H (fp16): per node, 32 groups of 8 halves (512 B per node):
//   [g*8+0..3] = K cols 4g..4g+3,  [g*8+4..7] = H cols 4g..4g+3
__device__ __half g_KH[N_NODES * 2 * F];
__device__ __half g_Qh[N_NODES * F];     // (feat @ Wq) * (1/sqrt(F))  fp16
__device__ int    g_deg[N_NODES];        // stays zero between invocations
__device__ int    g_rowStart[N_NODES + 1];
__device__ int    g_rank[N_EDGES];       // edge's rank within its dst node
__device__ int    g_srcOff[N_EDGES];     // src node id << 9 (BYTE offset in g_KH)
__device__ int    g_bsum[NBLK];

// ---------------------------------------------------------------------------
// hist: count degrees AND record each edge's arrival rank (atomicAdd return).
__global__ void hist_kernel(const int* __restrict__ dst) {
    int base = (blockIdx.x * blockDim.x + threadIdx.x) << 2;   // 4 edges/thread
    if (base + 3 < N_EDGES) {
        int4 d = *(const int4*)(dst + base);
        int4 r;
        r.x = atomicAdd(&g_deg[d.x], 1);
        r.y = atomicAdd(&g_deg[d.y], 1);
        r.z = atomicAdd(&g_deg[d.z], 1);
        r.w = atomicAdd(&g_deg[d.w], 1);
        *(int4*)(g_rank + base) = r;
    } else {
        for (int e = base; e < N_EDGES; e++)
            g_rank[e] = atomicAdd(&g_deg[__ldg(&dst[e])], 1);
    }
}

// block-local exclusive scan of deg -> rowStart(local), block totals -> bsum.
// Zeroes g_deg after reading (invariant for next invocation).
__global__ __launch_bounds__(256) void scan1_kernel() {
    __shared__ int s[256];
    int tid = threadIdx.x;
    int i = blockIdx.x * 256 + tid;
    int v = 0;
    if (i < N_NODES) { v = g_deg[i]; g_deg[i] = 0; }
    s[tid] = v;
    __syncthreads();
#pragma unroll
    for (int off = 1; off < 256; off <<= 1) {
        int t = (tid >= off) ? s[tid - off] : 0;
        __syncthreads();
        s[tid] += t;
        __syncthreads();
    }
    if (i < N_NODES) g_rowStart[i] = s[tid] - v;
    if (tid == 255) g_bsum[blockIdx.x] = s[255];
}

// add block offsets (each block reduces bsum[t < blockIdx] itself); sentinel.
__global__ __launch_bounds__(256) void scan23_kernel() {
    __shared__ int red[256];
    int tid = threadIdx.x;
    int v = (tid < NBLK && tid < blockIdx.x) ? g_bsum[tid] : 0;
    red[tid] = v;
    __syncthreads();
#pragma unroll
    for (int off = 128; off > 0; off >>= 1) {
        if (tid < off) red[tid] += red[tid + off];
        __syncthreads();
    }
    int offset = red[0];

    int i = blockIdx.x * 256 + tid;
    if (i < N_NODES) g_rowStart[i] += offset;
    if (i == 0) g_rowStart[N_NODES] = N_EDGES;
}

// atomic-free scatter: slot = rowStart[dst] + rank[edge]
__global__ void scatter_kernel(const int* __restrict__ src,
                               const int* __restrict__ dst) {
    int base = (blockIdx.x * blockDim.x + threadIdx.x) << 2;   // 4 edges/thread
    if (base + 3 < N_EDGES) {
        int4 d = *(const int4*)(dst + base);
        int4 s = *(const int4*)(src + base);
        int4 r = *(const int4*)(g_rank + base);
        g_srcOff[g_rowStart[d.x] + r.x] = s.x << 9;
        g_srcOff[g_rowStart[d.y] + r.y] = s.y << 9;
        g_srcOff[g_rowStart[d.z] + r.z] = s.z << 9;
        g_srcOff[g_rowStart[d.w] + r.w] = s.w << 9;
    } else {
        for (int e = base; e < N_EDGES; e++) {
            int d = __ldg(&dst[e]);
            g_srcOff[g_rowStart[d] + g_rank[e]] = __ldg(&src[e]) << 9;
        }
    }
}

// ---------------------------------------------------------------------------
__device__ __forceinline__ uint32_t f2tf32(float x) {
    uint32_t r;
    asm("cvt.rna.tf32.f32 %0, %1;" : "=r"(r) : "f"(x));
    return r;
}

// Fused 3-way GEMM (tf32 tensor cores): one 128x128 row tile per CTA;
// A staged ONCE, the three weights staged sequentially into Bs.
// H (j=0) and K (j=2) write fp16 into the interleaved g_KH;
// Q (j=1) writes fp16 pre-scaled by 1/sqrt(F) into g_Qh.
__global__ __launch_bounds__(256) void gemm3_tf32_kernel(
    const float* __restrict__ feat,
    const float* __restrict__ Wfc,
    const float* __restrict__ Wq,
    const float* __restrict__ Wk)
{
    extern __shared__ float sm[];
    float* As = sm;                 // [128][LDA]
    float* Bs = sm + 128 * LDA;     // [128][LDB]

    const int tid  = threadIdx.x;
    const int row0 = blockIdx.x * 128;

    for (int i = tid; i < 4096; i += 256) {
        int r = i >> 5, c4 = (i & 31) << 2;
        float4 v = make_float4(0.f, 0.f, 0.f, 0.f);
        if (row0 + r < N_NODES)
            v = *(const float4*)(feat + (size_t)(row0 + r) * F + c4);
        *(float4*)(As + r * LDA + c4) = v;
    }

    const int wid  = tid >> 5;
    const int lane = tid & 31;
    const int wm   = (wid & 3) << 5;
    const int wn   = (wid >> 2) << 6;
    const int grp  = lane >> 2;
    const int qid  = lane & 3;

    const float* Ws[3] = { Wfc, Wq, Wk };

#pragma unroll
    for (int j = 0; j < 3; j++) {
        __syncthreads();
        const float* W = Ws[j];
        for (int i = tid; i < 4096; i += 256) {
            int r = i >> 5, c4 = (i & 31) << 2;
            *(float4*)(Bs + r * LDB + c4) = *(const float4*)(W + r * F + c4);
        }
        __syncthreads();

        float acc[2][8][4];
#pragma unroll
        for (int mi = 0; mi < 2; mi++)
#pragma unroll
            for (int nt = 0; nt < 8; nt++)
#pragma unroll
                for (int c = 0; c < 4; c++) acc[mi][nt][c] = 0.0f;

#pragma unroll
        for (int ks = 0; ks < 16; ks++) {
            const int k0 = ks << 3;
            uint32_t a[2][4];
#pragma unroll
            for (int mi = 0; mi < 2; mi++) {
                const int rb = wm + (mi << 4);
                a[mi][0] = f2tf32(As[(rb + grp)     * LDA + k0 + qid]);
                a[mi][1] = f2tf32(As[(rb + grp + 8) * LDA + k0 + qid]);
                a[mi][2] = f2tf32(As[(rb + grp)     * LDA + k0 + qid + 4]);
                a[mi][3] = f2tf32(As[(rb + grp + 8) * LDA + k0 + qid + 4]);
            }
#pragma unroll
            for (int nt = 0; nt < 8; nt++) {
                const int n0 = wn + (nt << 3);
                uint32_t b0 = f2tf32(Bs[(k0 + qid)     * LDB + n0 + grp]);
                uint32_t b1 = f2tf32(Bs[(k0 + qid + 4) * LDB + n0 + grp]);
#pragma unroll
                for (int mi = 0; mi < 2; mi++) {
                    asm volatile(
                        "mma.sync.aligned.m16n8k8.row.col.f32.tf32.tf32.f32 "
                        "{%0,%1,%2,%3}, {%4,%5,%6,%7}, {%8,%9}, {%0,%1,%2,%3};"
                        : "+f"(acc[mi][nt][0]), "+f"(acc[mi][nt][1]),
                          "+f"(acc[mi][nt][2]), "+f"(acc[mi][nt][3])
                        : "r"(a[mi][0]), "r"(a[mi][1]), "r"(a[mi][2]),
                          "r"(a[mi][3]), "r"(b0), "r"(b1));
                }
            }
        }

        const int khOff = (j == 0) ? 4 : 0;   // H -> slot+4, K -> slot+0
#pragma unroll
        for (int mi = 0; mi < 2; mi++) {
            const int r = row0 + wm + (mi << 4) + grp;
#pragma unroll
            for (int nt = 0; nt < 8; nt++) {
                const int col = wn + (nt << 3) + (qid << 1);   // col even
                if (j == 1) {          // Q fp16, pre-scaled
                    if (r < N_NODES)
                        *(__half2*)(g_Qh + (size_t)r * F + col) =
                            __floats2half2_rn(acc[mi][nt][0] * SCALE_INV,
                                              acc[mi][nt][1] * SCALE_INV);
                    if (r + 8 < N_NODES)
                        *(__half2*)(g_Qh + (size_t)(r + 8) * F + col) =
                            __floats2half2_rn(acc[mi][nt][2] * SCALE_INV,
                                              acc[mi][nt][3] * SCALE_INV);
                } else {               // H/K fp16 interleaved
                    const int slot = ((col >> 2) << 3) + khOff + (col & 3);
                    if (r < N_NODES)
                        *(__half2*)(g_KH + (size_t)r * 256 + slot) =
                            __floats2half2_rn(acc[mi][nt][0], acc[mi][nt][1]);
                    if (r + 8 < N_NODES)
                        *(__half2*)(g_KH + (size_t)(r + 8) * 256 + slot) =
                            __floats2half2_rn(acc[mi][nt][2], acc[mi][nt][3]);
                }
            }
        }
    }
}

// ---------------------------------------------------------------------------
// Fused attention: ONE warp per dst node (R9 skeleton), ILP-4 batches with
// partitioned warp reduction; fp16 HFMA2 score path (q pre-scaled fp16).
// ---------------------------------------------------------------------------
__global__ __launch_bounds__(256) void fused_attn_kernel(float* __restrict__ out)
{
    int gw = (blockIdx.x * blockDim.x + threadIdx.x) >> 5;   // node id
    if (gw >= N_NODES) return;
    int lane = threadIdx.x & 31;

    int beg = g_rowStart[gw];
    int end = g_rowStart[gw + 1];

    float* orow = out + (size_t)gw * F + lane * 4;
    if (beg == end) {
        *(float4*)orow = make_float4(0.f, 0.f, 0.f, 0.f);
        return;
    }

    // q for this lane's 4 dims, fp16 (pre-scaled)
    uint2 qraw = *(const uint2*)(g_Qh + (unsigned)(gw * F + lane * 4));
    __half2 qh0 = *(__half2*)&qraw.x;
    __half2 qh1 = *(__half2*)&qraw.y;

    float ax = 0.f, ay = 0.f, az = 0.f, aw = 0.f;
    float den = 0.f;
    const unsigned lo = (unsigned)(lane << 4);   // byte offset within row
    const int g = lane >> 3;                     // lane group 0..3
    const char* base = (const char*)g_KH;

    for (int chunk = beg; chunk < end; chunk += 32) {
        int idx = chunk + lane;
        int myO = (idx < end) ? __ldg(&g_srcOff[idx]) : 0;
        int m = end - chunk; if (m > 32) m = 32;

        int j = 0;
        for (; j + 4 <= m; j += 4) {
            unsigned o0 = (unsigned)__shfl_sync(0xFFFFFFFFu, myO, j)     + lo;
            unsigned o1 = (unsigned)__shfl_sync(0xFFFFFFFFu, myO, j + 1) + lo;
            unsigned o2 = (unsigned)__shfl_sync(0xFFFFFFFFu, myO, j + 2) + lo;
            unsigned o3 = (unsigned)__shfl_sync(0xFFFFFFFFu, myO, j + 3) + lo;
            uint4 c0 = *(const uint4*)(base + o0);
            uint4 c1 = *(const uint4*)(base + o1);
            uint4 c2 = *(const uint4*)(base + o2);
            uint4 c3 = *(const uint4*)(base + o3);

            // fp16 dot partials (2 half2 ops each), then to fp32
            __half2 p0 = __hmul2(qh0, *(__half2*)&c0.x);
            __half2 p1 = __hmul2(qh0, *(__half2*)&c1.x);
            __half2 p2 = __hmul2(qh0, *(__half2*)&c2.x);
            __half2 p3 = __hmul2(qh0, *(__half2*)&c3.x);
            p0 = __hfma2(qh1, *(__half2*)&c0.y, p0);
            p1 = __hfma2(qh1, *(__half2*)&c1.y, p1);
            p2 = __hfma2(qh1, *(__half2*)&c2.y, p2);
            p3 = __hfma2(qh1, *(__half2*)&c3.y, p3);
            float2 f0 = __half22float2(p0);
            float2 f1 = __half22float2(p1);
            float2 f2 = __half22float2(p2);
            float2 f3 = __half22float2(p3);
            float v0 = f0.x + f0.y;
            float v1 = f1.x + f1.y;
            float v2 = f2.x + f2.y;
            float v3 = f3.x + f3.y;

            // partitioned reduction: levels 16,8 on all four
            v0 += __shfl_xor_sync(0xFFFFFFFFu, v0, 16);
            v1 += __shfl_xor_sync(0xFFFFFFFFu, v1, 16);
            v2 += __shfl_xor_sync(0xFFFFFFFFu, v2, 16);
            v3 += __shfl_xor_sync(0xFFFFFFFFu, v3, 16);
            v0 += __shfl_xor_sync(0xFFFFFFFFu, v0, 8);
            v1 += __shfl_xor_sync(0xFFFFFFFFu, v1, 8);
            v2 += __shfl_xor_sync(0xFFFFFFFFu, v2, 8);
            v3 += __shfl_xor_sync(0xFFFFFFFFu, v3, 8);
            float x = v0;
            x = (g == 1) ? v1 : x;
            x = (g == 2) ? v2 : x;
            x = (g == 3) ? v3 : x;
            x += __shfl_xor_sync(0xFFFFFFFFu, x, 4);
            x += __shfl_xor_sync(0xFFFFFFFFu, x, 2);
            x += __shfl_xor_sync(0xFFFFFFFFu, x, 1);
            float y = __expf(x);                     // ONE exp per lane
            float e0 = __shfl_sync(0xFFFFFFFFu, y, 0);
            float e1 = __shfl_sync(0xFFFFFFFFu, y, 8);
            float e2 = __shfl_sync(0xFFFFFFFFu, y, 16);
            float e3 = __shfl_sync(0xFFFFFFFFu, y, 24);

            // H side: unpack fp16 -> fp32, accumulate fp32
            float2 h0a = __half22float2(*(__half2*)&c0.z);
            float2 h0b = __half22float2(*(__half2*)&c0.w);
            float2 h1a = __half22float2(*(__half2*)&c1.z);
            float2 h1b = __half22float2(*(__half2*)&c1.w);
            float2 h2a = __half22float2(*(__half2*)&c2.z);
            float2 h2b = __half22float2(*(__half2*)&c2.w);
            float2 h3a = __half22float2(*(__half2*)&c3.z);
            float2 h3b = __half22float2(*(__half2*)&c3.w);

            den += (e0 + e1) + (e2 + e3);
            ax += e0*h0a.x + e1*h1a.x + e2*h2a.x + e3*h3a.x;
            ay += e0*h0a.y + e1*h1a.y + e2*h2a.y + e3*h3a.y;
            az += e0*h0b.x + e1*h1b.x + e2*h2b.x + e3*h3b.x;
            aw += e0*h0b.y + e1*h1b.y + e2*h2b.y + e3*h3b.y;
        }
        for (; j < m; j++) {
            unsigned o0 = (unsigned)__shfl_sync(0xFFFFFFFFu, myO, j) + lo;
            uint4 raw = *(const uint4*)(base + o0);
            __half2 p = __hmul2(qh0, *(__half2*)&raw.x);
            p = __hfma2(qh1, *(__half2*)&raw.y, p);
            float2 pf = __half22float2(p);
            float v0 = pf.x + pf.y;
#pragma unroll
            for (int o = 16; o > 0; o >>= 1)
                v0 += __shfl_xor_sync(0xFFFFFFFFu, v0, o);
            float e0 = __expf(v0);
            float2 ha = __half22float2(*(__half2*)&raw.z);
            float2 hb = __half22float2(*(__half2*)&raw.w);
            den += e0;
            ax += e0*ha.x; ay += e0*ha.y; az += e0*hb.x; aw += e0*hb.y;
        }
    }

    float inv = 1.0f / den;
    *(float4*)orow = make_float4(ax * inv, ay * inv, az * inv, aw * inv);
}

// ---------------------------------------------------------------------------
// Inputs: 0 feat, 1 loc, 2 W_fc, 3 Wq, 4 Wk, 5 Wq2, 6 Wk2, 7 G_w, 8 embed,
// 9 boundaries, 10 src, 11 dst, 12 inter_ids  (e2 branch is dead code)
// ---------------------------------------------------------------------------
extern "C" void kernel_launch(void* const* d_in, const int* in_sizes, int n_in,
                              void* d_out, int out_size)
{
    const float* feat = (const float*)d_in[0];
    const float* Wfc  = (const float*)d_in[2];
    const float* Wq   = (const float*)d_in[3];
    const float* Wk   = (const float*)d_in[4];
    const int*   src  = (const int*)d_in[10];
    const int*   dst  = (const int*)d_in[11];
    float* out = (float*)d_out;

    static cudaStream_t s2 = nullptr;
    static cudaEvent_t evFork = nullptr, evJoin = nullptr;
    if (!s2) {
        cudaFuncSetAttribute(gemm3_tf32_kernel,
                             cudaFuncAttributeMaxDynamicSharedMemorySize,
                             SMEM_BYTES);
        cudaStreamCreateWithFlags(&s2, cudaStreamNonBlocking);
        cudaEventCreateWithFlags(&evFork, cudaEventDisableTiming);
        cudaEventCreateWithFlags(&evJoin, cudaEventDisableTiming);
    }

    // fork: CSR build on s2, GEMM on the main (capture) stream
    cudaEventRecord(evFork, 0);
    cudaStreamWaitEvent(s2, evFork, 0);

    {   // --- s2: CSR build (rank-based, atomic-free scatter) ---
        int t4 = (N_EDGES + 3) / 4;
        hist_kernel<<<(t4 + 255) / 256, 256, 0, s2>>>(dst);
        scan1_kernel<<<NBLK, 256, 0, s2>>>();
        scan23_kernel<<<NBLK, 256, 0, s2>>>();
        scatter_kernel<<<(t4 + 255) / 256, 256, 0, s2>>>(src, dst);
        cudaEventRecord(evJoin, s2);
    }

    // --- main stream: H, Q, K GEMMs ---
    gemm3_tf32_kernel<<<(N_NODES + 127) / 128, 256, SMEM_BYTES>>>(
        feat, Wfc, Wq, Wk);

    // join, then fused attention (1 warp per node)
    cudaStreamWaitEvent(0, evJoin, 0);
    fused_attn_kernel<<<(N_NODES * 32 + 255) / 256, 256>>>(out);
}